// round 3
// baseline (speedup 1.0000x reference)
#include <cuda_runtime.h>
#include <cuda_fp16.h>
#include <cstdint>

// out = tanh(x @ W^T + b); x (131072, 256) fp32, W (256,256) fp32, b (256) fp32.
//
// Portable tensor path (harness lowers via compute_103 PTX, so NO tcgen05):
// warp-level mma.sync.m16n8k16 f16xf16->f32.
//   - W converted to fp16 and held ENTIRELY IN REGISTERS: warp w owns the
//     32-wide n-slice [w*32, w*32+32) for all K=256 -> 128 fp16x2 regs/thread.
//   - x streamed in 64-token tiles: cp.async fp32 -> SMEM stage, convert pass
//     -> fp16 SMEM (double-buffered, ldmatrix-swizzled), ldmatrix.x4 A frags.
//   - epilogue: + b, tanh.approx.f32 (1 MUFU), coalesced float2 stores.
// Persistent 148 CTAs x 256 threads.

#define HID      256
#define MT       64           // tokens per tile
#define NT       2048         // 131072 / 64
#define GRID     148
#define NTHREADS 256

// SMEM map (bytes): fp32 stage (64x256x4 = 64KB), two fp16 bufs (32KB each)
#define SM_STAGE 0u
#define SM_B0    65536u
#define SM_B1    (65536u + 32768u)
#define SMEM_TOTAL (65536 + 2 * 32768)

// ---------------------------------------------------------------- helpers ----

__device__ __forceinline__ uint32_t smem_u32(const void* p) {
    uint32_t a;
    asm("{ .reg .u64 t; cvta.to.shared.u64 t, %1; cvt.u32.u64 %0, t; }"
        : "=r"(a) : "l"(p));
    return a;
}

__device__ __forceinline__ void cp_async16(uint32_t dst, const void* src) {
    asm volatile("cp.async.cg.shared.global [%0], [%1], 16;"
                 :: "r"(dst), "l"(src) : "memory");
}
__device__ __forceinline__ void cp_commit() {
    asm volatile("cp.async.commit_group;" ::: "memory");
}
__device__ __forceinline__ void cp_wait0() {
    asm volatile("cp.async.wait_group 0;" ::: "memory");
}

__device__ __forceinline__ void sts64(uint32_t addr, uint32_t a, uint32_t b) {
    asm volatile("st.shared.v2.u32 [%0], {%1, %2};" :: "r"(addr), "r"(a), "r"(b));
}

__device__ __forceinline__ void lds128(uint32_t* r, uint32_t addr) {
    asm volatile("ld.shared.v4.u32 {%0, %1, %2, %3}, [%4];"
                 : "=r"(r[0]), "=r"(r[1]), "=r"(r[2]), "=r"(r[3]) : "r"(addr));
}

__device__ __forceinline__ void ldsm_x4(uint32_t* r, uint32_t addr) {
    asm volatile("ldmatrix.sync.aligned.m8n8.x4.shared.b16 {%0, %1, %2, %3}, [%4];"
                 : "=r"(r[0]), "=r"(r[1]), "=r"(r[2]), "=r"(r[3]) : "r"(addr));
}

__device__ __forceinline__ void mma16816(float* d, const uint32_t* a,
                                         const uint32_t* bfr) {
    asm volatile(
        "mma.sync.aligned.m16n8k16.row.col.f32.f16.f16.f32 "
        "{%0, %1, %2, %3}, {%4, %5, %6, %7}, {%8, %9}, {%0, %1, %2, %3};"
        : "+f"(d[0]), "+f"(d[1]), "+f"(d[2]), "+f"(d[3])
        : "r"(a[0]), "r"(a[1]), "r"(a[2]), "r"(a[3]), "r"(bfr[0]), "r"(bfr[1]));
}

__device__ __forceinline__ float tanh_f(float y) {
    float r;
    asm("tanh.approx.f32 %0, %1;" : "=f"(r) : "f"(y));
    return r;
}

// fill fp32 stage with tile t (coalesced 16B cp.async)
__device__ __forceinline__ void fill_stage(const float* __restrict__ x, int t,
                                           uint32_t sb, int tid) {
    const char* src = (const char*)(x + (size_t)t * MT * HID);
#pragma unroll
    for (int i = 0; i < 16; i++) {
        int g = tid + i * NTHREADS;            // 0..4095 16B chunks
        cp_async16(sb + SM_STAGE + (uint32_t)g * 16u, src + (size_t)g * 16);
    }
}

// convert fp32 stage -> fp16 buffer (ldmatrix-swizzled: 64 rows x 512B,
// 16B chunk index c16 XOR'ed with (row & 7))
__device__ __forceinline__ void convert_tile(uint32_t sb, uint32_t dst, int tid) {
#pragma unroll
    for (int i = 0; i < 16; i++) {
        int g = tid + i * NTHREADS;            // float4 index; row-major
        uint32_t r[4];
        lds128(r, sb + SM_STAGE + (uint32_t)g * 16u);
        float2 v01 = make_float2(__uint_as_float(r[0]), __uint_as_float(r[1]));
        float2 v23 = make_float2(__uint_as_float(r[2]), __uint_as_float(r[3]));
        __half2 h0 = __floats2half2_rn(v01.x, v01.y);
        __half2 h1 = __floats2half2_rn(v23.x, v23.y);
        uint32_t row = (uint32_t)(g >> 6);     // 64 float4 per row
        uint32_t c4  = (uint32_t)(g & 63);
        uint32_t c16 = c4 >> 1;
        uint32_t addr = dst + row * 512u + ((c16 ^ (row & 7u)) << 4) + (c4 & 1u) * 8u;
        sts64(addr, *(const uint32_t*)&h0, *(const uint32_t*)&h1);
    }
}

// ----------------------------------------------------------------- kernel ----

__global__ void __launch_bounds__(NTHREADS, 1)
rotor_kernel(const float* __restrict__ x, const float* __restrict__ W,
             const float* __restrict__ b, float* __restrict__ out) {
    extern __shared__ char smem[];
    const uint32_t sb = smem_u32(smem);
    const int tid = threadIdx.x;
    const int w = tid >> 5;
    const int l = tid & 31;

    // --- W -> registers. Warp w owns n in [w*32, w*32+32).
    // B frag (m16n8k16 col): thread t: b0 = {W[n][k], W[n][k+1]},
    // b1 = {W[n][k+8], W[n][k+9]}; n = base + natom*8 + (l>>2), k = ks*16 + (l&3)*2.
    uint32_t wreg[4][16][2];
    {
        const float2* Wv = (const float2*)W;
        const int nb = w * 32 + (l >> 2);
        const int kb = (l & 3) * 2;
#pragma unroll
        for (int na = 0; na < 4; na++) {
            const int n = nb + na * 8;
#pragma unroll
            for (int ks = 0; ks < 16; ks++) {
                const int k = ks * 16 + kb;
                float2 f0 = Wv[n * 128 + (k >> 1)];
                float2 f1 = Wv[n * 128 + ((k + 8) >> 1)];
                __half2 h0 = __floats2half2_rn(f0.x, f0.y);
                __half2 h1 = __floats2half2_rn(f1.x, f1.y);
                wreg[na][ks][0] = *(const uint32_t*)&h0;
                wreg[na][ks][1] = *(const uint32_t*)&h1;
            }
        }
    }

    // --- bias for this thread's output columns
    float2 bb[4];
    {
        const int n = w * 32 + (l & 3) * 2;
#pragma unroll
        for (int na = 0; na < 4; na++)
            bb[na] = *(const float2*)&b[n + na * 8];
    }

    // --- prologue: tile t0 -> stage -> fp16 buf0
    int t = blockIdx.x;
    fill_stage(x, t, sb, tid);
    cp_commit();
    cp_wait0();
    __syncthreads();
    convert_tile(sb, sb + SM_B0, tid);
    __syncthreads();

    int iter = 0;
    for (; t < NT; t += GRID, iter++) {
        const int p = iter & 1;
        const uint32_t bufp = sb + (p ? SM_B1 : SM_B0);
        const bool have_next = (t + GRID) < NT;

        // issue DRAM loads for next tile (stage is free: converted last iter)
        if (have_next) fill_stage(x, t + GRID, sb, tid);
        cp_commit();

        // --- GEMM: D[m 64][n 32] += x_tile[m][k] * W[n][k], K = 256
        float acc[4][4][4];
#pragma unroll
        for (int ma = 0; ma < 4; ma++)
#pragma unroll
            for (int na = 0; na < 4; na++)
#pragma unroll
                for (int c = 0; c < 4; c++) acc[ma][na][c] = 0.0f;

#pragma unroll
        for (int ks = 0; ks < 16; ks++) {
            uint32_t a[4][4];
#pragma unroll
            for (int ma = 0; ma < 4; ma++) {
                const uint32_t row = (uint32_t)(ma * 16 + (l & 15));
                const uint32_t c16 = (uint32_t)(ks * 2 + (l >> 4));
                ldsm_x4(a[ma], bufp + row * 512u + ((c16 ^ (row & 7u)) << 4));
            }
#pragma unroll
            for (int ma = 0; ma < 4; ma++)
#pragma unroll
                for (int na = 0; na < 4; na++)
                    mma16816(acc[ma][na], a[ma], wreg[na][ks]);
        }

        // --- next tile arrived; convert into the other fp16 buffer
        cp_wait0();
        __syncthreads();
        if (have_next) convert_tile(sb, sb + (p ? SM_B0 : SM_B1), tid);

        // --- epilogue: tanh(acc + b) -> out, coalesced float2 stores
        const int m0 = t * MT;
#pragma unroll
        for (int ma = 0; ma < 4; ma++) {
            const int r0 = m0 + ma * 16 + (l >> 2);
#pragma unroll
            for (int na = 0; na < 4; na++) {
                const int n = w * 32 + na * 8 + (l & 3) * 2;
                float2 v0, v1;
                v0.x = tanh_f(acc[ma][na][0] + bb[na].x);
                v0.y = tanh_f(acc[ma][na][1] + bb[na].y);
                v1.x = tanh_f(acc[ma][na][2] + bb[na].x);
                v1.y = tanh_f(acc[ma][na][3] + bb[na].y);
                *(float2*)&out[(size_t)r0 * HID + n] = v0;
                *(float2*)&out[(size_t)(r0 + 8) * HID + n] = v1;
            }
        }
        __syncthreads();   // buf(1-p) ready; stage free for next issue
    }
}

// ----------------------------------------------------------------- launch ----

extern "C" void kernel_launch(void* const* d_in, const int* in_sizes, int n_in,
                              void* d_out, int out_size) {
    const float* x = (const float*)d_in[0];
    const float* W = (const float*)d_in[1];
    const float* b = (const float*)d_in[2];
    float* out = (float*)d_out;
    cudaFuncSetAttribute(rotor_kernel,
                         cudaFuncAttributeMaxDynamicSharedMemorySize, SMEM_TOTAL);
    rotor_kernel<<<GRID, NTHREADS, SMEM_TOTAL>>>(x, W, b, out);
}

// round 4
// speedup vs baseline: 1.0644x; 1.0644x over previous
#include <cuda_runtime.h>
#include <cuda_fp16.h>
#include <cstdint>

// out = tanh(x @ W^T + b); x (131072, 256) fp32, W (256,256) fp32, b (256) fp32.
//
// mma.sync m16n8k16 f16->f32 (compute_103-portable; tcgen05 rejected by the
// harness's non-'a' PTX target). W fp16 register-stationary (warp owns a
// 32-wide n-slice), x streamed as 64-token tiles.
//
// Round-4 structure: 2 fp32 stages + 2 fp16 buffers; fill(t+2) issued at iter
// start (waited next iter -> DRAM latency fully hidden); convert(t+1)
// interleaved INTO the GEMM ks-loop (LSU dual-issues under tensor pipe);
// single syncthreads per iter.

#define HID      256
#define MT       64
#define NT       2048
#define GRID     148
#define NTHREADS 256

// SMEM map (bytes)
#define SM_S0    0u
#define SM_S1    65536u
#define SM_B0    131072u
#define SM_B1    163840u
#define SMEM_TOTAL (2 * 65536 + 2 * 32768)

// ---------------------------------------------------------------- helpers ----

__device__ __forceinline__ uint32_t smem_u32(const void* p) {
    uint32_t a;
    asm("{ .reg .u64 t; cvta.to.shared.u64 t, %1; cvt.u32.u64 %0, t; }"
        : "=r"(a) : "l"(p));
    return a;
}

__device__ __forceinline__ void cp_async16(uint32_t dst, const void* src) {
    asm volatile("cp.async.cg.shared.global [%0], [%1], 16;"
                 :: "r"(dst), "l"(src) : "memory");
}
__device__ __forceinline__ void cp_commit() {
    asm volatile("cp.async.commit_group;" ::: "memory");
}
__device__ __forceinline__ void cp_wait0() {
    asm volatile("cp.async.wait_group 0;" ::: "memory");
}
__device__ __forceinline__ void cp_wait1() {
    asm volatile("cp.async.wait_group 1;" ::: "memory");
}

__device__ __forceinline__ void sts64(uint32_t addr, uint32_t a, uint32_t b) {
    asm volatile("st.shared.v2.u32 [%0], {%1, %2};" :: "r"(addr), "r"(a), "r"(b));
}

__device__ __forceinline__ void lds128(uint32_t* r, uint32_t addr) {
    asm volatile("ld.shared.v4.u32 {%0, %1, %2, %3}, [%4];"
                 : "=r"(r[0]), "=r"(r[1]), "=r"(r[2]), "=r"(r[3]) : "r"(addr));
}

__device__ __forceinline__ void ldsm_x4(uint32_t* r, uint32_t addr) {
    asm volatile("ldmatrix.sync.aligned.m8n8.x4.shared.b16 {%0, %1, %2, %3}, [%4];"
                 : "=r"(r[0]), "=r"(r[1]), "=r"(r[2]), "=r"(r[3]) : "r"(addr));
}

__device__ __forceinline__ void mma16816(float* d, const uint32_t* a,
                                         const uint32_t* bfr) {
    asm volatile(
        "mma.sync.aligned.m16n8k16.row.col.f32.f16.f16.f32 "
        "{%0, %1, %2, %3}, {%4, %5, %6, %7}, {%8, %9}, {%0, %1, %2, %3};"
        : "+f"(d[0]), "+f"(d[1]), "+f"(d[2]), "+f"(d[3])
        : "r"(a[0]), "r"(a[1]), "r"(a[2]), "r"(a[3]), "r"(bfr[0]), "r"(bfr[1]));
}

__device__ __forceinline__ float tanh_f(float y) {
    float r;
    asm("tanh.approx.f32 %0, %1;" : "=f"(r) : "f"(y));
    return r;
}

// coalesced 16B cp.async fill of one fp32 tile into a stage buffer
__device__ __forceinline__ void fill_stage(const float* __restrict__ x, int t,
                                           uint32_t stage, int tid) {
    const char* src = (const char*)(x + (size_t)t * MT * HID);
#pragma unroll
    for (int i = 0; i < 16; i++) {
        int g = tid + i * NTHREADS;
        cp_async16(stage + (uint32_t)g * 16u, src + (size_t)g * 16);
    }
}

// one 1/16 slice of the fp32->fp16 convert (ldmatrix-swizzled dest)
__device__ __forceinline__ void convert_chunk(uint32_t src, uint32_t dst,
                                              int tid, int i) {
    int g = tid + i * NTHREADS;
    uint32_t r[4];
    lds128(r, src + (uint32_t)g * 16u);
    __half2 h0 = __floats2half2_rn(__uint_as_float(r[0]), __uint_as_float(r[1]));
    __half2 h1 = __floats2half2_rn(__uint_as_float(r[2]), __uint_as_float(r[3]));
    uint32_t row = (uint32_t)(g >> 6);
    uint32_t c4  = (uint32_t)(g & 63);
    uint32_t c16 = c4 >> 1;
    uint32_t addr = dst + row * 512u + ((c16 ^ (row & 7u)) << 4) + (c4 & 1u) * 8u;
    sts64(addr, *(const uint32_t*)&h0, *(const uint32_t*)&h1);
}

// ----------------------------------------------------------------- kernel ----

__global__ void __launch_bounds__(NTHREADS, 1)
rotor_kernel(const float* __restrict__ x, const float* __restrict__ W,
             const float* __restrict__ b, float* __restrict__ out) {
    extern __shared__ char smem[];
    const uint32_t sb = smem_u32(smem);
    const int tid = threadIdx.x;
    const int w = tid >> 5;
    const int l = tid & 31;

    const int t0 = blockIdx.x;

    // --- prologue: two fills in flight before anything waits
    fill_stage(x, t0, sb + SM_S0, tid);
    cp_commit();
    if (t0 + GRID < NT) fill_stage(x, t0 + GRID, sb + SM_S1, tid);
    cp_commit();

    // --- W -> registers (hidden under fill latency). Warp w owns n in
    // [w*32, w*32+32). B frag (m16n8k16 col-major):
    //   b0 = {W[n][k], W[n][k+1]}, b1 = {W[n][k+8], W[n][k+9]},
    //   n = w*32 + na*8 + (l>>2), k = ks*16 + (l&3)*2.
    uint32_t wreg[4][16][2];
    {
        const float2* Wv = (const float2*)W;
        const int nb = w * 32 + (l >> 2);
        const int kb = (l & 3) * 2;
#pragma unroll
        for (int na = 0; na < 4; na++) {
            const int n = nb + na * 8;
#pragma unroll
            for (int ks = 0; ks < 16; ks++) {
                const int k = ks * 16 + kb;
                float2 f0 = Wv[n * 128 + (k >> 1)];
                float2 f1 = Wv[n * 128 + ((k + 8) >> 1)];
                __half2 h0 = __floats2half2_rn(f0.x, f0.y);
                __half2 h1 = __floats2half2_rn(f1.x, f1.y);
                wreg[na][ks][0] = *(const uint32_t*)&h0;
                wreg[na][ks][1] = *(const uint32_t*)&h1;
            }
        }
    }
    float2 bb[4];
    {
        const int n = w * 32 + (l & 3) * 2;
#pragma unroll
        for (int na = 0; na < 4; na++)
            bb[na] = *(const float2*)&b[n + na * 8];
    }

    // --- convert tile t0 (stage0). Self-chunks only -> cp_wait1 suffices;
    // cross-thread visibility established by the iter-0 syncthreads.
    cp_wait1();
#pragma unroll
    for (int i = 0; i < 16; i++)
        convert_chunk(sb + SM_S0, sb + SM_B0, tid, i);

    int iter = 0;
    for (int t = t0; t < NT; t += GRID, iter++) {
        const int p = iter & 1;
        const uint32_t bufg = sb + (p ? SM_B1 : SM_B0);   // GEMM source
        const uint32_t bufc = sb + (p ? SM_B0 : SM_B1);   // convert dest (t+1)
        const uint32_t stc  = sb + ((iter & 1) ? SM_S0 : SM_S1); // convert src
        const uint32_t stf  = sb + ((iter & 1) ? SM_S1 : SM_S0); // fill dest
        const bool have_next = (t + GRID) < NT;

        // fill(t+1) arrived (committed a full iteration ago).
        cp_wait0();
        // Single barrier per iter. Orders: (a) prior iter's GEMM reads of bufc
        // before this iter's convert writes; (b) prior convert/STS of bufg
        // before this iter's ldsm; (c) stage stf free (its reader ran inside
        // the previous GEMM loop); (d) cp.async data visible cross-thread.
        __syncthreads();

        // issue fill(t+2) now -> waited next iter, never exposed
        if (t + 2 * GRID < NT) fill_stage(x, t + 2 * GRID, stf, tid);
        cp_commit();

        // --- GEMM (tile t) with convert(t+1) interleaved into the ks loop
        float acc[4][4][4];
#pragma unroll
        for (int ma = 0; ma < 4; ma++)
#pragma unroll
            for (int na = 0; na < 4; na++)
#pragma unroll
                for (int c = 0; c < 4; c++) acc[ma][na][c] = 0.0f;

#pragma unroll
        for (int ks = 0; ks < 16; ks++) {
            uint32_t a[4][4];
#pragma unroll
            for (int ma = 0; ma < 4; ma++) {
                const uint32_t row = (uint32_t)(ma * 16 + (l & 15));
                const uint32_t c16 = (uint32_t)(ks * 2 + (l >> 4));
                ldsm_x4(a[ma], bufg + row * 512u + ((c16 ^ (row & 7u)) << 4));
            }
            if (have_next) convert_chunk(stc, bufc, tid, ks);
#pragma unroll
            for (int ma = 0; ma < 4; ma++)
#pragma unroll
                for (int na = 0; na < 4; na++)
                    mma16816(acc[ma][na], a[ma], wreg[na][ks]);
        }

        // --- epilogue: tanh(acc + b) -> out (coalesced float2, streaming)
        const int m0 = t * MT;
#pragma unroll
        for (int ma = 0; ma < 4; ma++) {
            const int r0 = m0 + ma * 16 + (l >> 2);
#pragma unroll
            for (int na = 0; na < 4; na++) {
                const int n = w * 32 + na * 8 + (l & 3) * 2;
                float2 v0, v1;
                v0.x = tanh_f(acc[ma][na][0] + bb[na].x);
                v0.y = tanh_f(acc[ma][na][1] + bb[na].y);
                v1.x = tanh_f(acc[ma][na][2] + bb[na].x);
                v1.y = tanh_f(acc[ma][na][3] + bb[na].y);
                __stcs((float2*)&out[(size_t)r0 * HID + n], v0);
                __stcs((float2*)&out[(size_t)(r0 + 8) * HID + n], v1);
            }
        }
    }
}

// ----------------------------------------------------------------- launch ----

extern "C" void kernel_launch(void* const* d_in, const int* in_sizes, int n_in,
                              void* d_out, int out_size) {
    const float* x = (const float*)d_in[0];
    const float* W = (const float*)d_in[1];
    const float* b = (const float*)d_in[2];
    float* out = (float*)d_out;
    cudaFuncSetAttribute(rotor_kernel,
                         cudaFuncAttributeMaxDynamicSharedMemorySize, SMEM_TOTAL);
    rotor_kernel<<<GRID, NTHREADS, SMEM_TOTAL>>>(x, W, b, out);
}

// round 5
// speedup vs baseline: 1.0717x; 1.0068x over previous
#include <cuda_runtime.h>
#include <cuda_fp16.h>
#include <cstdint>

// out = tanh(x @ W^T + b); x (131072, 256) fp32, W (256,256) fp32, b (256) fp32.
//
// mma.sync m16n8k16 f16->f32 (compute_103-portable; tcgen05 rejected by the
// harness's non-'a' PTX target). W fp16 register-stationary (warp owns a
// 32-wide n-slice), x streamed as 64-token tiles; 2 fp32 cp.async stages +
// 2 fp16 ldmatrix-swizzled buffers.
//
// Round-5: single flattened 64-step (ma,ks) GEMM pipeline per tile with
//   - 2-deep A-fragment rotation (ldsm j+1 issued at step j),
//   - epilogue of m-atom (ma-1) interleaved into steps of ma (MUFU+STG
//     dual-issue under the tensor pipe),
//   - fp32->fp16 convert of tile t+1 spread through ma=0's steps.

#define HID      256
#define MT       64
#define NT       2048
#define GRID     148
#define NTHREADS 256

#define SM_S0    0u
#define SM_S1    65536u
#define SM_B0    131072u
#define SM_B1    163840u
#define SMEM_TOTAL (2 * 65536 + 2 * 32768)

// ---------------------------------------------------------------- helpers ----

__device__ __forceinline__ uint32_t smem_u32(const void* p) {
    uint32_t a;
    asm("{ .reg .u64 t; cvta.to.shared.u64 t, %1; cvt.u32.u64 %0, t; }"
        : "=r"(a) : "l"(p));
    return a;
}

__device__ __forceinline__ void cp_async16(uint32_t dst, const void* src) {
    asm volatile("cp.async.cg.shared.global [%0], [%1], 16;"
                 :: "r"(dst), "l"(src) : "memory");
}
__device__ __forceinline__ void cp_commit() {
    asm volatile("cp.async.commit_group;" ::: "memory");
}
__device__ __forceinline__ void cp_wait0() {
    asm volatile("cp.async.wait_group 0;" ::: "memory");
}
__device__ __forceinline__ void cp_wait1() {
    asm volatile("cp.async.wait_group 1;" ::: "memory");
}

__device__ __forceinline__ void sts64(uint32_t addr, uint32_t a, uint32_t b) {
    asm volatile("st.shared.v2.u32 [%0], {%1, %2};" :: "r"(addr), "r"(a), "r"(b));
}

__device__ __forceinline__ void lds128(uint32_t* r, uint32_t addr) {
    asm volatile("ld.shared.v4.u32 {%0, %1, %2, %3}, [%4];"
                 : "=r"(r[0]), "=r"(r[1]), "=r"(r[2]), "=r"(r[3]) : "r"(addr));
}

__device__ __forceinline__ void ldsm_x4(uint32_t* r, uint32_t addr) {
    asm volatile("ldmatrix.sync.aligned.m8n8.x4.shared.b16 {%0, %1, %2, %3}, [%4];"
                 : "=r"(r[0]), "=r"(r[1]), "=r"(r[2]), "=r"(r[3]) : "r"(addr));
}

__device__ __forceinline__ void mma16816(float* d, const uint32_t* a,
                                         const uint32_t* bfr) {
    asm volatile(
        "mma.sync.aligned.m16n8k16.row.col.f32.f16.f16.f32 "
        "{%0, %1, %2, %3}, {%4, %5, %6, %7}, {%8, %9}, {%0, %1, %2, %3};"
        : "+f"(d[0]), "+f"(d[1]), "+f"(d[2]), "+f"(d[3])
        : "r"(a[0]), "r"(a[1]), "r"(a[2]), "r"(a[3]), "r"(bfr[0]), "r"(bfr[1]));
}

__device__ __forceinline__ float tanh_f(float y) {
    float r;
    asm("tanh.approx.f32 %0, %1;" : "=f"(r) : "f"(y));
    return r;
}

__device__ __forceinline__ void fill_stage(const float* __restrict__ x, int t,
                                           uint32_t stage, int tid) {
    const char* src = (const char*)(x + (size_t)t * MT * HID);
#pragma unroll
    for (int i = 0; i < 16; i++) {
        int g = tid + i * NTHREADS;
        cp_async16(stage + (uint32_t)g * 16u, src + (size_t)g * 16);
    }
}

__device__ __forceinline__ void convert_chunk(uint32_t src, uint32_t dst,
                                              int tid, int i) {
    int g = tid + i * NTHREADS;
    uint32_t r[4];
    lds128(r, src + (uint32_t)g * 16u);
    __half2 h0 = __floats2half2_rn(__uint_as_float(r[0]), __uint_as_float(r[1]));
    __half2 h1 = __floats2half2_rn(__uint_as_float(r[2]), __uint_as_float(r[3]));
    uint32_t row = (uint32_t)(g >> 6);
    uint32_t c4  = (uint32_t)(g & 63);
    uint32_t c16 = c4 >> 1;
    uint32_t addr = dst + row * 512u + ((c16 ^ (row & 7u)) << 4) + (c4 & 1u) * 8u;
    sts64(addr, *(const uint32_t*)&h0, *(const uint32_t*)&h1);
}

// ----------------------------------------------------------------- kernel ----

__global__ void __launch_bounds__(NTHREADS, 1)
rotor_kernel(const float* __restrict__ x, const float* __restrict__ W,
             const float* __restrict__ b, float* __restrict__ out) {
    extern __shared__ char smem[];
    const uint32_t sb = smem_u32(smem);
    const int tid = threadIdx.x;
    const int w = tid >> 5;
    const int l = tid & 31;

    const int t0 = blockIdx.x;

    // --- prologue: two fills in flight before anything waits
    fill_stage(x, t0, sb + SM_S0, tid);
    cp_commit();
    if (t0 + GRID < NT) fill_stage(x, t0 + GRID, sb + SM_S1, tid);
    cp_commit();

    // --- W -> registers (hidden under fill latency). Warp w owns n in
    // [w*32, w*32+32). B frag (m16n8k16 col): b0={W[n][k],W[n][k+1]},
    // b1={W[n][k+8],W[n][k+9]}; n = w*32+na*8+(l>>2), k = ks*16+(l&3)*2.
    uint32_t wreg[4][16][2];
    {
        const float2* Wv = (const float2*)W;
        const int nb = w * 32 + (l >> 2);
        const int kb = (l & 3) * 2;
#pragma unroll
        for (int na = 0; na < 4; na++) {
            const int n = nb + na * 8;
#pragma unroll
            for (int ks = 0; ks < 16; ks++) {
                const int k = ks * 16 + kb;
                float2 f0 = Wv[n * 128 + (k >> 1)];
                float2 f1 = Wv[n * 128 + ((k + 8) >> 1)];
                __half2 h0 = __floats2half2_rn(f0.x, f0.y);
                __half2 h1 = __floats2half2_rn(f1.x, f1.y);
                wreg[na][ks][0] = *(const uint32_t*)&h0;
                wreg[na][ks][1] = *(const uint32_t*)&h1;
            }
        }
    }
    float2 bb[4];
    {
        const int n = w * 32 + (l & 3) * 2;
#pragma unroll
        for (int na = 0; na < 4; na++)
            bb[na] = *(const float2*)&b[n + na * 8];
    }

    // per-thread fixed output base: row (l>>2), col w*32+(l&3)*2
    float* const obase = out + (size_t)(l >> 2) * HID + w * 32 + (l & 3) * 2;

    // --- convert tile t0 (stage0); own chunks only -> cp_wait1 suffices
    cp_wait1();
#pragma unroll
    for (int i = 0; i < 16; i++)
        convert_chunk(sb + SM_S0, sb + SM_B0, tid, i);

    int iter = 0;
    for (int t = t0; t < NT; t += GRID, iter++) {
        const int p = iter & 1;
        const uint32_t bufg = sb + (p ? SM_B1 : SM_B0);          // GEMM src
        const uint32_t bufc = sb + (p ? SM_B0 : SM_B1);          // convert dst
        const uint32_t stc  = sb + ((iter & 1) ? SM_S0 : SM_S1); // convert src
        const uint32_t stf  = sb + ((iter & 1) ? SM_S1 : SM_S0); // fill dst
        const bool have_next = (t + GRID) < NT;

        cp_wait0();          // fill(t+1) arrived (committed one iter ago)
        __syncthreads();     // orders buf/stage reuse + cp.async visibility

        if (t + 2 * GRID < NT) fill_stage(x, t + 2 * GRID, stf, tid);
        cp_commit();

        float acc[4][4][4];
#pragma unroll
        for (int ma = 0; ma < 4; ma++)
#pragma unroll
            for (int na = 0; na < 4; na++)
#pragma unroll
                for (int c = 0; c < 4; c++) acc[ma][na][c] = 0.0f;

        float* const op = obase + (size_t)t * MT * HID;

        // --- flattened 64-step pipeline: j = ma*16 + ks
        //  step j: ldsm frag(j+1); [convert (ma=0) | epilogue piece of ma-1];
        //          4x mma with frag(j).
        uint32_t af[2][4];
        {
            const uint32_t row = (uint32_t)(l & 15);
            const uint32_t c16 = (uint32_t)(l >> 4);
            ldsm_x4(af[0], bufg + row * 512u + ((c16 ^ (row & 7u)) << 4));
        }
#pragma unroll
        for (int j = 0; j < 64; j++) {
            const int ma = j >> 4;
            const int ks = j & 15;
            if (j < 63) {
                const int jn = j + 1;
                const uint32_t row = (uint32_t)(((jn >> 4) << 4) + (l & 15));
                const uint32_t c16 = (uint32_t)(((jn & 15) << 1) + (l >> 4));
                ldsm_x4(af[jn & 1], bufg + row * 512u + ((c16 ^ (row & 7u)) << 4));
            }
            if (ma == 0) {
                if (have_next) convert_chunk(stc, bufc, tid, ks);
            } else if ((ks & 3) == 3) {
                // epilogue piece: acc[ma-1], na = ks>>2
                const int me = ma - 1, na = ks >> 2;
                float2 v0, v1;
                v0.x = tanh_f(acc[me][na][0] + bb[na].x);
                v0.y = tanh_f(acc[me][na][1] + bb[na].y);
                v1.x = tanh_f(acc[me][na][2] + bb[na].x);
                v1.y = tanh_f(acc[me][na][3] + bb[na].y);
                __stcs((float2*)(op + (size_t)me * 16 * HID + na * 8), v0);
                __stcs((float2*)(op + (size_t)(me * 16 + 8) * HID + na * 8), v1);
            }
#pragma unroll
            for (int na = 0; na < 4; na++)
                mma16816(acc[ma][na], af[j & 1], wreg[na][ks]);
        }

        // exposed tail: epilogue of ma = 3
#pragma unroll
        for (int na = 0; na < 4; na++) {
            float2 v0, v1;
            v0.x = tanh_f(acc[3][na][0] + bb[na].x);
            v0.y = tanh_f(acc[3][na][1] + bb[na].y);
            v1.x = tanh_f(acc[3][na][2] + bb[na].x);
            v1.y = tanh_f(acc[3][na][3] + bb[na].y);
            __stcs((float2*)(op + (size_t)48 * HID + na * 8), v0);
            __stcs((float2*)(op + (size_t)56 * HID + na * 8), v1);
        }
    }
}

// ----------------------------------------------------------------- launch ----

extern "C" void kernel_launch(void* const* d_in, const int* in_sizes, int n_in,
                              void* d_out, int out_size) {
    const float* x = (const float*)d_in[0];
    const float* W = (const float*)d_in[1];
    const float* b = (const float*)d_in[2];
    float* out = (float*)d_out;
    cudaFuncSetAttribute(rotor_kernel,
                         cudaFuncAttributeMaxDynamicSharedMemorySize, SMEM_TOTAL);
    rotor_kernel<<<GRID, NTHREADS, SMEM_TOTAL>>>(x, W, b, out);
}